// round 6
// baseline (speedup 1.0000x reference)
#include <cuda_runtime.h>
#include <cuda_bf16.h>

// Problem shape (fixed by reference)
#define VOCAB   1000000
#define EMB     64
#define BATCH   4096
#define SLOTS   26
#define MAX_NNZ 10

static constexpr int PAIRS = BATCH * SLOTS;          // 106,496 (b,s) pairs
static constexpr int LANES_PER_PAIR = 16;            // 16 threads x float4 = 64 floats
static constexpr int THREADS = 256;

// One (batch,slot) pair per 16-thread group. Each lane owns 4 embedding dims
// (float4) -> each table-row gather is a fully coalesced 256B read (LDG.E.128
// x16 lanes). Keys+mask preloaded into registers so ptxas can front-batch the
// predicated gathers (high MLP -> DRAM latency hidden). Masked rows are NOT
// loaded at all (saves ~40% of gather bandwidth at 60% density).
//
// Mask is read as int32 words with a !=0 test: correct whether the harness
// promoted the jax bool to int32 (0/1) or float32 (0x0 / 0x3F800000).
__global__ __launch_bounds__(THREADS)
void emb_lookup_kernel(const int* __restrict__ keys,
                       const int* __restrict__ mask,
                       const float* __restrict__ table,
                       float* __restrict__ out)
{
    const int gid  = blockIdx.x * THREADS + threadIdx.x;
    const int pair = gid >> 4;          // (b*SLOTS + s)
    const int lane = gid & 15;          // which float4 of the 64-dim vector
    if (pair >= PAIRS) return;

    const int base = pair * MAX_NNZ;

    // Preload keys + mask (broadcast across the 16-thread group; L1 hits).
    int  k[MAX_NNZ];
    bool m[MAX_NNZ];
#pragma unroll
    for (int n = 0; n < MAX_NNZ; n++) {
        k[n] = keys[base + n];
        m[n] = (mask[base + n] != 0);   // works for int32 0/1 AND float32 0.0/1.0 bits
    }

    // Two independent accumulators to shorten the FADD dependency chain.
    float4 acc0 = make_float4(0.f, 0.f, 0.f, 0.f);
    float4 acc1 = make_float4(0.f, 0.f, 0.f, 0.f);
    int cnt = 0;

#pragma unroll
    for (int n = 0; n < MAX_NNZ; n++) {
        if (m[n]) {
            const float4 v = *reinterpret_cast<const float4*>(
                table + (size_t)k[n] * EMB + lane * 4);
            if (n & 1) {
                acc1.x += v.x; acc1.y += v.y; acc1.z += v.z; acc1.w += v.w;
            } else {
                acc0.x += v.x; acc0.y += v.y; acc0.z += v.z; acc0.w += v.w;
            }
            cnt++;
        }
    }

    const float inv = 1.0f / (float)(cnt > 0 ? cnt : 1);
    float4 r;
    r.x = (acc0.x + acc1.x) * inv;
    r.y = (acc0.y + acc1.y) * inv;
    r.z = (acc0.z + acc1.z) * inv;
    r.w = (acc0.w + acc1.w) * inv;

    *reinterpret_cast<float4*>(out + (size_t)pair * EMB + lane * 4) = r;
}

extern "C" void kernel_launch(void* const* d_in, const int* in_sizes, int n_in,
                              void* d_out, int out_size)
{
    const int*   keys  = (const int*)d_in[0];
    const int*   mask  = (const int*)d_in[1];
    const float* table = (const float*)d_in[2];
    float*       out   = (float*)d_out;

    const int total_threads = PAIRS * LANES_PER_PAIR;
    const int blocks = (total_threads + THREADS - 1) / THREADS;
    emb_lookup_kernel<<<blocks, THREADS>>>(keys, mask, table, out);
}

// round 9
// speedup vs baseline: 1.0570x; 1.0570x over previous
#include <cuda_runtime.h>
#include <cuda_bf16.h>

// Problem shape (fixed by reference)
#define VOCAB   1000000
#define EMB     64
#define BATCH   4096
#define SLOTS   26
#define MAX_NNZ 10

static constexpr int PAIRS = BATCH * SLOTS;          // 106,496 (b,s) pairs
static constexpr int LANES_PER_PAIR = 16;            // 16 threads x float4 = 64 floats
static constexpr int THREADS = 256;

// One (batch,slot) pair per 16-thread group; each lane owns one float4 of the
// 64-dim vector, so a row gather is a fully coalesced 256B read and one
// LDG.E.128 warp instruction covers 512B (two pairs' rows).
//
// R7 changes vs R6 (33.2us, DRAM busy only 60%):
//  - keys+mask loaded as int2 vectors (offset pair*40B is 8B-aligned):
//    10 LDG.64 instead of 20 scalar LDGs -> ~half the LSU issue pressure.
//  - gathers explicitly batched 2 waves x 5 deep into a register array:
//    MLP_p1 ~5 instead of ~2-3, hiding the ~577cyc DRAM latency better.
//  - output stored with __stcs (streaming) so the 27MB of writes don't evict
//    the ~121MB unique table footprint from the 126MB L2.
__global__ __launch_bounds__(THREADS)
void emb_lookup_kernel(const int* __restrict__ keys,
                       const int* __restrict__ mask,
                       const float* __restrict__ table,
                       float* __restrict__ out)
{
    const int gid  = blockIdx.x * THREADS + threadIdx.x;
    const int pair = gid >> 4;          // (b*SLOTS + s)
    const int lane = gid & 15;          // which float4 of the 64-dim vector
    if (pair >= PAIRS) return;

    const int base = pair * MAX_NNZ;

    // Vectorized key/mask preload: 5x int2 each (40B per pair, 8B aligned).
    const int2* kp = reinterpret_cast<const int2*>(keys + base);
    const int2* mp = reinterpret_cast<const int2*>(mask + base);
    int  k[MAX_NNZ];
    bool m[MAX_NNZ];
#pragma unroll
    for (int j = 0; j < 5; j++) {
        const int2 kk = kp[j];
        const int2 mm = mp[j];
        k[2*j]   = kk.x;  k[2*j+1] = kk.y;
        m[2*j]   = (mm.x != 0);          // works for int32 0/1 AND f32 0.0/1.0 bits
        m[2*j+1] = (mm.y != 0);
    }

    int cnt = 0;
#pragma unroll
    for (int n = 0; n < MAX_NNZ; n++) cnt += m[n] ? 1 : 0;

    float4 acc = make_float4(0.f, 0.f, 0.f, 0.f);

    // Two waves of 5 batched, predicated gathers. Zero-init + @P LDG keeps
    // 5 independent float4 loads in flight before any FADD consumes one.
#pragma unroll
    for (int w = 0; w < 2; w++) {
        float4 v[5];
#pragma unroll
        for (int j = 0; j < 5; j++) {
            const int n = w * 5 + j;
            v[j] = make_float4(0.f, 0.f, 0.f, 0.f);
            if (m[n]) {
                v[j] = *reinterpret_cast<const float4*>(
                    table + (size_t)k[n] * EMB + lane * 4);
            }
        }
#pragma unroll
        for (int j = 0; j < 5; j++) {
            acc.x += v[j].x; acc.y += v[j].y;
            acc.z += v[j].z; acc.w += v[j].w;
        }
    }

    const float inv = 1.0f / (float)(cnt > 0 ? cnt : 1);
    float4 r;
    r.x = acc.x * inv;
    r.y = acc.y * inv;
    r.z = acc.z * inv;
    r.w = acc.w * inv;

    // Streaming store: evict-first in L2, protect the table's resident set.
    __stcs(reinterpret_cast<float4*>(out + (size_t)pair * EMB + lane * 4), r);
}

extern "C" void kernel_launch(void* const* d_in, const int* in_sizes, int n_in,
                              void* d_out, int out_size)
{
    const int*   keys  = (const int*)d_in[0];
    const int*   mask  = (const int*)d_in[1];
    const float* table = (const float*)d_in[2];
    float*       out   = (float*)d_out;

    const int total_threads = PAIRS * LANES_PER_PAIR;
    const int blocks = (total_threads + THREADS - 1) / THREADS;
    emb_lookup_kernel<<<blocks, THREADS>>>(keys, mask, table, out);
}